// round 17
// baseline (speedup 1.0000x reference)
#include <cuda_runtime.h>
#include <cuda_bf16.h>
#include <cstdint>

// LeftPool: out[b,c,h,w] = max(x[b,c,h,w:]) — reverse cummax along width (=128, contiguous).
//
// 256-bit IO variant: memory treated as 1KB ROW-PAIRS (2 x 512B rows).
// Each warp owns 4 row-pairs strided by P = npairs/4 (keeps the verified
// 4-wide-stream layout from R6). One ld.global.v8.f32 per pair: lanes 0-15
// cover the even row, lanes 16-31 the odd row; the lane-suffix scan runs at
// width 16 (4 shfl steps). Doubles outstanding bytes-in-flight per thread
// (4 x 32B) and halves LDG/STG count vs the float4 version.

__device__ __forceinline__ void ldg_v8(float* v, const float* p) {
    asm volatile("ld.global.v8.f32 {%0,%1,%2,%3,%4,%5,%6,%7}, [%8];"
        : "=f"(v[0]), "=f"(v[1]), "=f"(v[2]), "=f"(v[3]),
          "=f"(v[4]), "=f"(v[5]), "=f"(v[6]), "=f"(v[7])
        : "l"(p));
}

__device__ __forceinline__ void stg_v8(float* p, const float* v) {
    asm volatile("st.global.v8.f32 [%0], {%1,%2,%3,%4,%5,%6,%7,%8};"
        :: "l"(p),
           "f"(v[0]), "f"(v[1]), "f"(v[2]), "f"(v[3]),
           "f"(v[4]), "f"(v[5]), "f"(v[6]), "f"(v[7])
        : "memory");
}

__global__ void __launch_bounds__(256) leftpool_kernel(
    const float* __restrict__ x, float* __restrict__ out, int P)
{
    const int gwarp = (int)((blockIdx.x * blockDim.x + threadIdx.x) >> 5);
    const int lane  = threadIdx.x & 31;
    if (gwarp >= P) return;

    const size_t pstride = (size_t)P * 256;                 // floats per quarter
    const size_t a0 = (size_t)gwarp * 256 + (size_t)lane * 8;  // float index
    const size_t a1 = a0 + pstride;
    const size_t a2 = a1 + pstride;
    const size_t a3 = a2 + pstride;

    // Front-batch all 4 x 256-bit loads.
    float v0[8], v1[8], v2[8], v3[8];
    ldg_v8(v0, x + a0);
    ldg_v8(v1, x + a1);
    ldg_v8(v2, x + a2);
    ldg_v8(v3, x + a3);

    // In-lane suffix max over 8 elements (4 independent chains interleave).
    #pragma unroll
    for (int i = 6; i >= 0; --i) {
        v0[i] = fmaxf(v0[i], v0[i + 1]);
        v1[i] = fmaxf(v1[i], v1[i + 1]);
        v2[i] = fmaxf(v2[i], v2[i + 1]);
        v3[i] = fmaxf(v3[i], v3[i + 1]);
    }

    // Inclusive suffix max across the 16 lanes of each half-warp (one row each).
    float m0 = v0[0], m1 = v1[0], m2 = v2[0], m3 = v3[0];
    #pragma unroll
    for (int d = 1; d < 16; d <<= 1) {
        float t0 = __shfl_down_sync(0xffffffffu, m0, d, 16);
        float t1 = __shfl_down_sync(0xffffffffu, m1, d, 16);
        float t2 = __shfl_down_sync(0xffffffffu, m2, d, 16);
        float t3 = __shfl_down_sync(0xffffffffu, m3, d, 16);
        m0 = fmaxf(m0, t0);   // out-of-segment shfl returns own value -> harmless
        m1 = fmaxf(m1, t1);
        m2 = fmaxf(m2, t2);
        m3 = fmaxf(m3, t3);
    }
    // Exclusive suffix: shift down by one within the half-warp; last lane -> -inf.
    float s0 = __shfl_down_sync(0xffffffffu, m0, 1, 16);
    float s1 = __shfl_down_sync(0xffffffffu, m1, 1, 16);
    float s2 = __shfl_down_sync(0xffffffffu, m2, 1, 16);
    float s3 = __shfl_down_sync(0xffffffffu, m3, 1, 16);
    if ((lane & 15) == 15) {
        const float ninf = __int_as_float(0xff800000u);
        s0 = ninf; s1 = ninf; s2 = ninf; s3 = ninf;
    }

    #pragma unroll
    for (int i = 0; i < 8; ++i) {
        v0[i] = fmaxf(v0[i], s0);
        v1[i] = fmaxf(v1[i], s1);
        v2[i] = fmaxf(v2[i], s2);
        v3[i] = fmaxf(v3[i], s3);
    }

    stg_v8(out + a0, v0);
    stg_v8(out + a1, v1);
    stg_v8(out + a2, v2);
    stg_v8(out + a3, v3);
}

extern "C" void kernel_launch(void* const* d_in, const int* in_sizes, int n_in,
                              void* d_out, int out_size)
{
    const float* x = (const float*)d_in[0];
    float* out = (float*)d_out;

    const int W = 128;                          // contiguous width axis
    const int nrows = in_sizes[0] / W;          // 524288
    const int npairs = nrows / 2;               // 262144 row-pairs (1KB each)
    const int P = npairs / 4;                   // 65536 warps, 4 pairs (8 rows) each

    const int threads = 256;                    // 8 warps/block
    const int warps_per_block = threads / 32;
    const int blocks = (P + warps_per_block - 1) / warps_per_block;  // 8192

    leftpool_kernel<<<blocks, threads>>>(x, out, P);
}